// round 12
// baseline (speedup 1.0000x reference)
#include <cuda_runtime.h>
#include <cuda_fp16.h>
#include <cstdint>

// out[i,j,k] = sum_d x[i+1,d]*x[j+1,d]*Wp[d,k] + b[k]
// (diff_term antisymmetric -> cancels under (i,j) symmetrization; prod_term symmetric)
//
// fp16 operands; A-plane built in-register (fp16(x)*fp16(w) via mul.f16x2).
// 136 triangular 32x32 tiles x split-K=4 -> 544 CTAs x 256 threads (8 warps:
// 2 planes x 2 M-halves x 2 N-halves, warp tile 16x16) -> ~29 warps/SM.
// 3-stage cp.async; epilogue red.global.add.v4.f32 both orientations.
// Output pre-filled with bias by prep kernel. Expected rel_err ~4.1e-4.

#define OUTN 510
#define DDIM 1280
#define NTB 16
#define NTRI 136
#define SPLITS 4
#define KPS 320             // K per split
#define KC 64               // K per chunk
#define NCH 5               // chunks per split
#define STG_BYTES 8192      // A 32x128B + B 32x128B
#define SB_OFF 4096
#define WB_OFF 24576        // w-buffer: 2 planes x 320 halves = 1280B
#define SMEM_REQ (WB_OFF + 1280 + 128)

__device__ __align__(128) __half g_Xh[512 * DDIM];

// ---------------- helpers ----------------
__device__ __forceinline__ uint32_t smem_u32(const void* p) {
    uint32_t a;
    asm("{ .reg .u64 t; cvta.to.shared.u64 t, %1; cvt.u32.u64 %0, t; }" : "=r"(a) : "l"(p));
    return a;
}
__device__ __forceinline__ uint32_t pk2h(float a, float b) {
    __half2 t = __floats2half2_rn(a, b);
    return *reinterpret_cast<uint32_t*>(&t);
}

#define CPA(dst, src) \
    asm volatile("cp.async.cg.shared.global [%0], [%1], 16;" :: "r"(dst), "l"(src))
#define CP_COMMIT() asm volatile("cp.async.commit_group;" ::: "memory")
#define CP_WAIT1()  asm volatile("cp.async.wait_group 1;" ::: "memory")
#define CP_WAIT0()  asm volatile("cp.async.wait_group 0;" ::: "memory")

#define LDSM4(r0, r1, r2, r3, addr) \
    asm volatile("ldmatrix.sync.aligned.m8n8.x4.shared.b16 {%0,%1,%2,%3}, [%4];" \
                 : "=r"(r0), "=r"(r1), "=r"(r2), "=r"(r3) : "r"(addr))

#define LDSB32(r, addr) \
    asm volatile("ld.shared.b32 %0, [%1];" : "=r"(r) : "r"(addr))

#define HMUL2(d, a, b) \
    asm("mul.f16x2 %0, %1, %2;" : "=r"(d) : "r"(a), "r"(b))

#define MMA16816(d, a, b0, b1) \
    asm volatile("mma.sync.aligned.m16n8k16.row.col.f32.f16.f16.f32 " \
                 "{%0,%1,%2,%3}, {%4,%5,%6,%7}, {%8,%9}, {%0,%1,%2,%3};" \
                 : "+f"(d[0]), "+f"(d[1]), "+f"(d[2]), "+f"(d[3]) \
                 : "r"(a[0]), "r"(a[1]), "r"(a[2]), "r"(a[3]), "r"(b0), "r"(b1))

#define REDV4(ptr, v0, v1, v2, v3) \
    asm volatile("red.global.add.v4.f32 [%0], {%1, %2, %3, %4};" \
                 :: "l"(ptr), "f"(v0), "f"(v1), "f"(v2), "f"(v3) : "memory")

// ---------------- prep: Xh fp16 plane + bias-fill output ----------------
__global__ __launch_bounds__(320, 4)
void prep_kernel(const float* __restrict__ x, const float* __restrict__ bias,
                 float* __restrict__ out) {
    const int r = blockIdx.x;          // 0..511
    const int d0 = threadIdx.x * 4;    // 0..1276
    const size_t p = (size_t)r * DDIM + d0;

    float4 xv = *(const float4*)&x[p];
    *(uint2*)&g_Xh[p] = make_uint2(pk2h(xv.x, xv.y), pk2h(xv.z, xv.w));

    // bias-fill output: 510*510*2 floats = 130050 float4 of (b0,b1,b0,b1)
    const int gtid = blockIdx.x * 320 + threadIdx.x;   // < 163840
    if (gtid < (OUTN * OUTN * 2) / 4) {
        const float b0 = bias[0], b1 = bias[1];
        ((float4*)out)[gtid] = make_float4(b0, b1, b0, b1);
    }
}

// ---------------- GEMM (split-K partial, REDV4 epilogue) ----------------
__global__ __launch_bounds__(256, 4)
void pcm_mma_kernel(float* __restrict__ out, const float* __restrict__ W) {
    extern __shared__ char smraw[];
    uint32_t sb = smem_u32(smraw);
    uint32_t base = (sb + 127) & ~127u;
    char* smc = smraw + (base - sb);

    // triangular tile decode
    int t = blockIdx.x, ti = 0;
    while (t >= NTB - ti) { t -= NTB - ti; ++ti; }
    int tj = ti + t;
    const int i0 = ti * 32, j0 = tj * 32;
    const int split = blockIdx.y;

    const int tid = threadIdx.x;
    const int w = tid >> 5, L = tid & 31;
    const int plane = w >> 2;            // k-plane 0/1
    const int mh = (w >> 1) & 1;         // M-half
    const int nh = w & 1;                // N-half

    // ---- w-buffer fill: wh[plane][k] = fp16(W[2*(split*KPS+k)+plane]), 640 halves
    {
        __half* wb = (__half*)(smc + WB_OFF);
#pragma unroll
        for (int u = 0; u < 3; u++) {
            const int idx = tid + u * 256;           // < 768, use < 640
            if (idx < 2 * KPS) {
                const int pp = (idx >= KPS) ? 1 : 0;
                const int k = idx - pp * KPS;
                wb[pp * KPS + k] = __float2half_rn(W[2 * (split * KPS + k) + pp]);
            }
        }
    }

    // ---- staged-load assignments: 64 rows x 8 col-groups = 512 x 16B, 2 per thread
    const __half* src[2];
    uint32_t dst[2];
#pragma unroll
    for (int u = 0; u < 2; u++) {
        const int idx = tid + u * 256;
        const int row = idx >> 3, cg = idx & 7;
        if (row < 32) {                  // A: i-tile X rows
            int gi = i0 + row + 1; if (gi > 511) gi = 511;
            src[u] = &g_Xh[(size_t)gi * DDIM + split * KPS + cg * 8];
            dst[u] = (uint32_t)(row * 128 + ((cg * 16) ^ ((row & 7) * 16)));
        } else {                          // B: j-tile X rows
            const int r = row - 32;
            int gj = j0 + r + 1; if (gj > 511) gj = 511;
            src[u] = &g_Xh[(size_t)gj * DDIM + split * KPS + cg * 8];
            dst[u] = (uint32_t)(SB_OFF + r * 128 + ((cg * 16) ^ ((r & 7) * 16)));
        }
    }

#define LOAD_CHUNK(c) do { \
    const uint32_t stg_ = base + ((c) % 3) * STG_BYTES; \
    _Pragma("unroll") \
    for (int u = 0; u < 2; u++) CPA(stg_ + dst[u], src[u] + (c) * KC); \
} while (0)

    // ---- fragment addressing: warp computes 16(i, mh-half) x 16(j, nh-half), one plane
    const int a_r = (L & 7) + ((L >> 3) & 1) * 8;      // 0..15
    const uint32_t a_cb0 = ((L >> 4) & 1) * 16;
    const uint32_t a_xm = (uint32_t)((a_r & 7) * 16);
    const uint32_t aRow = (uint32_t)(mh * 16 + a_r) * 128;
    const int b_r = nh * 16 + (L & 7) + ((L >> 4) & 1) * 8;
    const uint32_t b_cb0 = ((L >> 3) & 1) * 16;
    const uint32_t b_xm = (uint32_t)((b_r & 7) * 16);
    const uint32_t bRow = SB_OFF + (uint32_t)b_r * 128;
    // w lookup base (byte addr): wb + plane*640 + (L&3)*4
    const uint32_t wBase = base + WB_OFF + (uint32_t)plane * 640 + (uint32_t)((L & 3) * 4);

    float acc[2][4];
#pragma unroll
    for (int n = 0; n < 2; n++)
#pragma unroll
        for (int e = 0; e < 4; e++) acc[n][e] = 0.f;

    LOAD_CHUNK(0);
    CP_COMMIT();
    LOAD_CHUNK(1);
    CP_COMMIT();

#pragma unroll
    for (int c = 0; c < NCH; c++) {
        if (c + 1 < NCH) CP_WAIT1(); else CP_WAIT0();
        __syncthreads();                 // chunk c + w-buffer visible; stage (c+2)%3 free

        if (c + 2 < NCH) {
            LOAD_CHUNK(c + 2);
            CP_COMMIT();
        }

        const uint32_t stg = base + (c % 3) * STG_BYTES;
        const uint32_t wChunk = wBase + (uint32_t)(c * KC * 2);
#pragma unroll
        for (int kk = 0; kk < 4; kk++) {
            const uint32_t colA = (a_cb0 + kk * 32) ^ a_xm;
            const uint32_t colB = (b_cb0 + kk * 32) ^ b_xm;
            uint32_t xa[4], bb[4];
            LDSM4(xa[0], xa[1], xa[2], xa[3], stg + aRow + colA);
            LDSM4(bb[0], bb[1], bb[2], bb[3], stg + bRow + colB);

            uint32_t wlo, whi;
            LDSB32(wlo, wChunk + kk * 32);          // w[k0], w[k0+1]
            LDSB32(whi, wChunk + kk * 32 + 16);     // w[k0+8], w[k0+9]

            uint32_t a0[4];
            HMUL2(a0[0], xa[0], wlo); HMUL2(a0[1], xa[1], wlo);
            HMUL2(a0[2], xa[2], whi); HMUL2(a0[3], xa[3], whi);

            MMA16816(acc[0], a0, bb[0], bb[1]);
            MMA16816(acc[1], a0, bb[2], bb[3]);
        }
    }

    // ---- epilogue: stage D (64x33: rows 0-31 k0, 32-63 k1) in stage-0 smem
    __syncthreads();                     // all LDSM reads done before overwrite
    float* Ds = (float*)smc;
    {
        const int er = L >> 2, ec = (L & 3) * 2;
        float* dp = &Ds[(plane * 32 + mh * 16 + er) * 33 + nh * 16 + ec];
        dp[0] = acc[0][0];          dp[1] = acc[0][1];
        dp[8 * 33] = acc[0][2];     dp[8 * 33 + 1] = acc[0][3];
        dp[8] = acc[1][0];          dp[9] = acc[1][1];
        dp[8 * 33 + 8] = acc[1][2]; dp[8 * 33 + 9] = acc[1][3];
    }
    __syncthreads();

    // main orientation: 512 REDV4 tasks (r 0..31, jp 0..15), lanes sweep jp
#pragma unroll
    for (int p = 0; p < 2; p++) {
        const int task = tid + p * 256;
        const int jp = task & 15, r = task >> 4;
        const int i = i0 + r, j = j0 + 2 * jp;
        if (i < OUTN && j < OUTN) {      // j even -> j+1 <= 509 < OUTN
            float* pp = &out[((size_t)i * OUTN + j) * 2];
            REDV4(pp, Ds[r * 33 + 2 * jp],     Ds[(r + 32) * 33 + 2 * jp],
                      Ds[r * 33 + 2 * jp + 1], Ds[(r + 32) * 33 + 2 * jp + 1]);
        }
    }

    // mirror orientation (skip diagonal tiles): lanes sweep ip
    if (ti != tj) {
#pragma unroll
        for (int p = 0; p < 2; p++) {
            const int task = tid + p * 256;
            const int ip = task & 15, cc = task >> 4;
            const int jj = j0 + cc, ig = i0 + 2 * ip;   // ig+1 <= 479 < OUTN
            if (jj < OUTN) {
                float* pp = &out[((size_t)jj * OUTN + ig) * 2];
                REDV4(pp, Ds[(2 * ip) * 33 + cc],     Ds[(2 * ip + 32) * 33 + cc],
                          Ds[(2 * ip + 1) * 33 + cc], Ds[(2 * ip + 33) * 33 + cc]);
            }
        }
    }
}

extern "C" void kernel_launch(void* const* d_in, const int* in_sizes, int n_in,
                              void* d_out, int out_size) {
    const float* x = (const float*)d_in[0];   // (1,512,1280) fp32
    const float* W = (const float*)d_in[1];   // (2560,2) fp32
    const float* b = (const float*)d_in[2];   // (2,) fp32
    float* out = (float*)d_out;               // (1,510,510,2) fp32

    prep_kernel<<<512, 320>>>(x, b, out);

    cudaFuncSetAttribute(pcm_mma_kernel,
                         cudaFuncAttributeMaxDynamicSharedMemorySize, SMEM_REQ);

    dim3 grid(NTRI, SPLITS);
    pcm_mma_kernel<<<grid, 256, SMEM_REQ>>>(out, W);
}

// round 13
// speedup vs baseline: 1.0127x; 1.0127x over previous
#include <cuda_runtime.h>
#include <cuda_fp16.h>
#include <cstdint>

// out[i,j,k] = sum_d x[i+1,d]*x[j+1,d]*Wp[d,k] + b[k]
// (diff_term antisymmetric -> cancels under (i,j) symmetrization; prod_term symmetric)
//
// fp16 operands; A-plane in-register (fp16(x)*fp16(w) via mul.f16x2).
// 136 triangular 32x32 tiles x split-K=4 -> 544 CTAs x 128 threads (warp 32x16).
// Mainloop: 3-stage cp.async + manual kk software-pipeline (double-buffered LDSM
// fragments) + per-chunk vectorized w-fragment loads (2x ld.shared.v4.b32).
// Epilogue: smem-staged tile -> red.global.add.v4.f32, both orientations.
// Output pre-filled with bias by prep kernel. Expected rel_err 4.139e-4.

#define OUTN 510
#define DDIM 1280
#define NTB 16
#define NTRI 136
#define SPLITS 4
#define KPS 320             // K per split
#define KC 64               // K per chunk
#define NCH 5               // chunks per split
#define STG_BYTES 8192      // A 32x128B + B 32x128B
#define SB_OFF 4096
#define WB_OFF 24576        // w-buffer: 2 planes x 5 chunks x 4 q x 8 words = 1280B
#define SMEM_REQ (WB_OFF + 1280 + 128)

__device__ __align__(128) __half g_Xh[512 * DDIM];

// ---------------- helpers ----------------
__device__ __forceinline__ uint32_t smem_u32(const void* p) {
    uint32_t a;
    asm("{ .reg .u64 t; cvta.to.shared.u64 t, %1; cvt.u32.u64 %0, t; }" : "=r"(a) : "l"(p));
    return a;
}
__device__ __forceinline__ uint32_t pk2h(float a, float b) {
    __half2 t = __floats2half2_rn(a, b);
    return *reinterpret_cast<uint32_t*>(&t);
}

#define CPA(dst, src) \
    asm volatile("cp.async.cg.shared.global [%0], [%1], 16;" :: "r"(dst), "l"(src))
#define CP_COMMIT() asm volatile("cp.async.commit_group;" ::: "memory")
#define CP_WAIT1()  asm volatile("cp.async.wait_group 1;" ::: "memory")
#define CP_WAIT0()  asm volatile("cp.async.wait_group 0;" ::: "memory")

#define LDSM4(r0, r1, r2, r3, addr) \
    asm volatile("ldmatrix.sync.aligned.m8n8.x4.shared.b16 {%0,%1,%2,%3}, [%4];" \
                 : "=r"(r0), "=r"(r1), "=r"(r2), "=r"(r3) : "r"(addr))

#define LDS128(r0, r1, r2, r3, addr) \
    asm volatile("ld.shared.v4.b32 {%0,%1,%2,%3}, [%4];" \
                 : "=r"(r0), "=r"(r1), "=r"(r2), "=r"(r3) : "r"(addr))

#define HMUL2(d, a, b) \
    asm("mul.f16x2 %0, %1, %2;" : "=r"(d) : "r"(a), "r"(b))

#define MMA16816(d, a, b0, b1) \
    asm volatile("mma.sync.aligned.m16n8k16.row.col.f32.f16.f16.f32 " \
                 "{%0,%1,%2,%3}, {%4,%5,%6,%7}, {%8,%9}, {%0,%1,%2,%3};" \
                 : "+f"(d[0]), "+f"(d[1]), "+f"(d[2]), "+f"(d[3]) \
                 : "r"(a[0]), "r"(a[1]), "r"(a[2]), "r"(a[3]), "r"(b0), "r"(b1))

#define REDV4(ptr, v0, v1, v2, v3) \
    asm volatile("red.global.add.v4.f32 [%0], {%1, %2, %3, %4};" \
                 :: "l"(ptr), "f"(v0), "f"(v1), "f"(v2), "f"(v3) : "memory")

// ---------------- prep: Xh fp16 plane + bias-fill output ----------------
__global__ __launch_bounds__(320, 4)
void prep_kernel(const float* __restrict__ x, const float* __restrict__ bias,
                 float* __restrict__ out) {
    const int r = blockIdx.x;          // 0..511
    const int d0 = threadIdx.x * 4;    // 0..1276
    const size_t p = (size_t)r * DDIM + d0;

    float4 xv = *(const float4*)&x[p];
    *(uint2*)&g_Xh[p] = make_uint2(pk2h(xv.x, xv.y), pk2h(xv.z, xv.w));

    // bias-fill output: 510*510*2 floats = 130050 float4 of (b0,b1,b0,b1)
    const int gtid = blockIdx.x * 320 + threadIdx.x;   // < 163840
    if (gtid < (OUTN * OUTN * 2) / 4) {
        const float b0 = bias[0], b1 = bias[1];
        ((float4*)out)[gtid] = make_float4(b0, b1, b0, b1);
    }
}

// ---------------- GEMM (split-K partial, REDV4 epilogue) ----------------
__global__ __launch_bounds__(128, 4)
void pcm_mma_kernel(float* __restrict__ out, const float* __restrict__ W) {
    extern __shared__ char smraw[];
    uint32_t sb = smem_u32(smraw);
    uint32_t base = (sb + 127) & ~127u;
    char* smc = smraw + (base - sb);

    // triangular tile decode
    int t = blockIdx.x, ti = 0;
    while (t >= NTB - ti) { t -= NTB - ti; ++ti; }
    int tj = ti + t;
    const int i0 = ti * 32, j0 = tj * 32;
    const int split = blockIdx.y;

    const int tid = threadIdx.x;
    const int w = tid >> 5, L = tid & 31;
    const int plane = w >> 1;            // warpM = k-plane
    const int warpN = w & 1;

    // ---- w-buffer fill, chunk-vectorized layout:
    // word index = plane*160 + c*32 + q*8 + (kk*2+h); value = (w[d], w[d+1]) halves
    // where d = split*KPS + c*64 + kk*16 + h*8 + q*2, column = plane.
    {
        uint32_t* wb = (uint32_t*)(smc + WB_OFF);
#pragma unroll
        for (int u = 0; u < 3; u++) {
            const int idx = tid + u * 128;           // < 384, use < 320
            if (idx < 320) {
                const int pl = (idx >= 160) ? 1 : 0;
                const int r = idx - pl * 160;
                const int c = r >> 5;
                const int r2 = r & 31;
                const int q = r2 >> 3;
                const int wd = r2 & 7;
                const int kk = wd >> 1, h = wd & 1;
                const int d = split * KPS + c * 64 + kk * 16 + h * 8 + q * 2;
                wb[idx] = pk2h(W[2 * d + pl], W[2 * (d + 1) + pl]);
            }
        }
    }

    // ---- staged-load assignments: 64 rows x 8 col-groups = 512 x 16B, 4 per thread
    const __half* src[4];
    uint32_t dst[4];
#pragma unroll
    for (int u = 0; u < 4; u++) {
        const int idx = tid + u * 128;
        const int row = idx >> 3, cg = idx & 7;
        if (row < 32) {                  // A: i-tile X rows
            int gi = i0 + row + 1; if (gi > 511) gi = 511;
            src[u] = &g_Xh[(size_t)gi * DDIM + split * KPS + cg * 8];
            dst[u] = (uint32_t)(row * 128 + ((cg * 16) ^ ((row & 7) * 16)));
        } else {                          // B: j-tile X rows
            const int r = row - 32;
            int gj = j0 + r + 1; if (gj > 511) gj = 511;
            src[u] = &g_Xh[(size_t)gj * DDIM + split * KPS + cg * 8];
            dst[u] = (uint32_t)(SB_OFF + r * 128 + ((cg * 16) ^ ((r & 7) * 16)));
        }
    }

#define LOAD_CHUNK(c) do { \
    const uint32_t stg_ = base + ((c) % 3) * STG_BYTES; \
    _Pragma("unroll") \
    for (int u = 0; u < 4; u++) CPA(stg_ + dst[u], src[u] + (c) * KC); \
} while (0)

    // ---- fragment addressing: warp computes 32(i) x 16(j) for its k-plane
    const int a_r0 = (L & 7) + ((L >> 3) & 1) * 8;     // 0..15
    const uint32_t a_cb0 = ((L >> 4) & 1) * 16;
    const uint32_t a_xm = (uint32_t)((a_r0 & 7) * 16);
    const uint32_t aRow0 = (uint32_t)a_r0 * 128;
    const uint32_t aRow1 = (uint32_t)(a_r0 + 16) * 128;
    const int b_r = warpN * 16 + (L & 7) + ((L >> 4) & 1) * 8;
    const uint32_t b_cb0 = ((L >> 3) & 1) * 16;
    const uint32_t b_xm = (uint32_t)((b_r & 7) * 16);
    const uint32_t bRow = SB_OFF + (uint32_t)b_r * 128;
    // per-chunk w-fragment base: wb + (plane*160 + q*8)*4, chunk stride 128B
    const uint32_t wBase = base + WB_OFF + (uint32_t)(plane * 640 + (L & 3) * 32);

    float acc[4][4];
#pragma unroll
    for (int n = 0; n < 4; n++)
#pragma unroll
        for (int e = 0; e < 4; e++) acc[n][e] = 0.f;

    LOAD_CHUNK(0);
    CP_COMMIT();
    LOAD_CHUNK(1);
    CP_COMMIT();

#pragma unroll
    for (int c = 0; c < NCH; c++) {
        if (c + 1 < NCH) CP_WAIT1(); else CP_WAIT0();
        __syncthreads();                 // chunk c + w-buffer visible; stage (c+2)%3 free

        if (c + 2 < NCH) {
            LOAD_CHUNK(c + 2);
            CP_COMMIT();
        }

        const uint32_t stg = base + (c % 3) * STG_BYTES;

        // w-fragments for the whole chunk: 8 words = 2x LDS.128
        uint32_t wf[8];
        {
            const uint32_t wa = wBase + (uint32_t)(c * 128);
            LDS128(wf[0], wf[1], wf[2], wf[3], wa);
            LDS128(wf[4], wf[5], wf[6], wf[7], wa + 16);
        }

        // kk software pipeline: double-buffered fragments
        uint32_t xa0[2][4], xa1[2][4], bb[2][4];
        {
            const uint32_t colA = a_cb0 ^ a_xm;
            const uint32_t colB = b_cb0 ^ b_xm;
            LDSM4(xa0[0][0], xa0[0][1], xa0[0][2], xa0[0][3], stg + aRow0 + colA);
            LDSM4(xa1[0][0], xa1[0][1], xa1[0][2], xa1[0][3], stg + aRow1 + colA);
            LDSM4(bb[0][0], bb[0][1], bb[0][2], bb[0][3], stg + bRow + colB);
        }
#pragma unroll
        for (int kk = 0; kk < 4; kk++) {
            const int cur = kk & 1, nxt = cur ^ 1;
            if (kk < 3) {
                const uint32_t colA = (a_cb0 + (kk + 1) * 32) ^ a_xm;
                const uint32_t colB = (b_cb0 + (kk + 1) * 32) ^ b_xm;
                LDSM4(xa0[nxt][0], xa0[nxt][1], xa0[nxt][2], xa0[nxt][3], stg + aRow0 + colA);
                LDSM4(xa1[nxt][0], xa1[nxt][1], xa1[nxt][2], xa1[nxt][3], stg + aRow1 + colA);
                LDSM4(bb[nxt][0], bb[nxt][1], bb[nxt][2], bb[nxt][3], stg + bRow + colB);
            }
            const uint32_t wlo = wf[kk * 2], whi = wf[kk * 2 + 1];
            uint32_t a0[4], a1[4];
            HMUL2(a0[0], xa0[cur][0], wlo); HMUL2(a0[1], xa0[cur][1], wlo);
            HMUL2(a0[2], xa0[cur][2], whi); HMUL2(a0[3], xa0[cur][3], whi);
            HMUL2(a1[0], xa1[cur][0], wlo); HMUL2(a1[1], xa1[cur][1], wlo);
            HMUL2(a1[2], xa1[cur][2], whi); HMUL2(a1[3], xa1[cur][3], whi);

            MMA16816(acc[0], a0, bb[cur][0], bb[cur][1]);
            MMA16816(acc[1], a0, bb[cur][2], bb[cur][3]);
            MMA16816(acc[2], a1, bb[cur][0], bb[cur][1]);
            MMA16816(acc[3], a1, bb[cur][2], bb[cur][3]);
        }
    }

    // ---- epilogue: stage D (64x33: rows 0-31 k0, 32-63 k1) in stage-0 smem
    __syncthreads();                     // all LDSM reads done before overwrite
    float* Ds = (float*)smc;
    {
        const int er = L >> 2, ec = (L & 3) * 2;
        float* dp = &Ds[(plane * 32 + er) * 33 + warpN * 16 + ec];
        dp[0] = acc[0][0];          dp[1] = acc[0][1];
        dp[8 * 33] = acc[0][2];     dp[8 * 33 + 1] = acc[0][3];
        dp[8] = acc[1][0];          dp[9] = acc[1][1];
        dp[8 * 33 + 8] = acc[1][2]; dp[8 * 33 + 9] = acc[1][3];
        float* dq = dp + 16 * 33;
        dq[0] = acc[2][0];          dq[1] = acc[2][1];
        dq[8 * 33] = acc[2][2];     dq[8 * 33 + 1] = acc[2][3];
        dq[8] = acc[3][0];          dq[9] = acc[3][1];
        dq[8 * 33 + 8] = acc[3][2]; dq[8 * 33 + 9] = acc[3][3];
    }
    __syncthreads();

    // main orientation: 512 REDV4 tasks (r 0..31, jp 0..15), lanes sweep jp
#pragma unroll
    for (int p = 0; p < 4; p++) {
        const int task = tid + p * 128;
        const int jp = task & 15, r = task >> 4;
        const int i = i0 + r, j = j0 + 2 * jp;
        if (i < OUTN && j < OUTN) {      // j even -> j+1 <= 509 < OUTN
            float* pp = &out[((size_t)i * OUTN + j) * 2];
            REDV4(pp, Ds[r * 33 + 2 * jp],     Ds[(r + 32) * 33 + 2 * jp],
                      Ds[r * 33 + 2 * jp + 1], Ds[(r + 32) * 33 + 2 * jp + 1]);
        }
    }

    // mirror orientation (skip diagonal tiles): lanes sweep ip
    if (ti != tj) {
#pragma unroll
        for (int p = 0; p < 4; p++) {
            const int task = tid + p * 128;
            const int ip = task & 15, cc = task >> 4;
            const int jj = j0 + cc, ig = i0 + 2 * ip;   // ig+1 <= 479 < OUTN
            if (jj < OUTN) {
                float* pp = &out[((size_t)jj * OUTN + ig) * 2];
                REDV4(pp, Ds[(2 * ip) * 33 + cc],     Ds[(2 * ip + 32) * 33 + cc],
                          Ds[(2 * ip + 1) * 33 + cc], Ds[(2 * ip + 33) * 33 + cc]);
            }
        }
    }
}

extern "C" void kernel_launch(void* const* d_in, const int* in_sizes, int n_in,
                              void* d_out, int out_size) {
    const float* x = (const float*)d_in[0];   // (1,512,1280) fp32
    const float* W = (const float*)d_in[1];   // (2560,2) fp32
    const float* b = (const float*)d_in[2];   // (2,) fp32
    float* out = (float*)d_out;               // (1,510,510,2) fp32

    prep_kernel<<<512, 320>>>(x, b, out);

    cudaFuncSetAttribute(pcm_mma_kernel,
                         cudaFuncAttributeMaxDynamicSharedMemorySize, SMEM_REQ);

    dim3 grid(NTRI, SPLITS);
    pcm_mma_kernel<<<grid, 128, SMEM_REQ>>>(out, W);
}

// round 15
// speedup vs baseline: 1.1881x; 1.1731x over previous
#include <cuda_runtime.h>
#include <cuda_fp16.h>
#include <cstdint>

// out[i,j,k] = sum_d x[i+1,d]*x[j+1,d]*Wp[d,k] + b[k]
// (diff_term antisymmetric -> cancels under (i,j) symmetrization; prod_term symmetric)
//
// fp16 operands; A-plane in-register (fp16(x)*fp16(w) via mul.f16x2).
// 136 triangular 32x32 tiles, ONE CTA per tile, 512 threads = 4 K-range groups
// x (2 planes x 2 N-halves). Each group: private 3-stage cp.async pipeline in its
// own 24KB smem region, named-barrier synced (no CTA-wide mainloop barriers).
// Epilogue: per-group area dump -> CTA reduce (+bias) -> plain st.global.v4 both
// orientations. No split-K atomics, no output prefill. Expected rel_err ~4.1e-4.

#define OUTN 510
#define DDIM 1280
#define NTB 16
#define NTRI 136
#define KPG 320             // K per group
#define KC 64               // K per chunk
#define NCH 5               // chunks per group
#define STG_BYTES 8192      // A 32x128B + B 32x128B
#define SB_OFF 4096
#define GROUP_BYTES 24576   // 3 stages
#define WB_OFF 98304        // 4 groups x 1280B w-buffers
#define DS_OFF 103424       // 64x33 floats = 8448B
#define SMEM_REQ (DS_OFF + 8448 + 64)

__device__ __align__(128) __half g_Xh[512 * DDIM];

// ---------------- helpers ----------------
__device__ __forceinline__ uint32_t smem_u32(const void* p) {
    uint32_t a;
    asm("{ .reg .u64 t; cvta.to.shared.u64 t, %1; cvt.u32.u64 %0, t; }" : "=r"(a) : "l"(p));
    return a;
}
__device__ __forceinline__ uint32_t pk2h(float a, float b) {
    __half2 t = __floats2half2_rn(a, b);
    return *reinterpret_cast<uint32_t*>(&t);
}

#define CPA(dst, src) \
    asm volatile("cp.async.cg.shared.global [%0], [%1], 16;" :: "r"(dst), "l"(src))
#define CP_COMMIT() asm volatile("cp.async.commit_group;" ::: "memory")
#define CP_WAIT1()  asm volatile("cp.async.wait_group 1;" ::: "memory")
#define CP_WAIT0()  asm volatile("cp.async.wait_group 0;" ::: "memory")

#define BARG(gid) asm volatile("bar.sync %0, 128;" :: "r"((gid) + 1) : "memory")

#define LDSM4(r0, r1, r2, r3, addr) \
    asm volatile("ldmatrix.sync.aligned.m8n8.x4.shared.b16 {%0,%1,%2,%3}, [%4];" \
                 : "=r"(r0), "=r"(r1), "=r"(r2), "=r"(r3) : "r"(addr))

#define LDS128(r0, r1, r2, r3, addr) \
    asm volatile("ld.shared.v4.b32 {%0,%1,%2,%3}, [%4];" \
                 : "=r"(r0), "=r"(r1), "=r"(r2), "=r"(r3) : "r"(addr))

#define HMUL2(d, a, b) \
    asm("mul.f16x2 %0, %1, %2;" : "=r"(d) : "r"(a), "r"(b))

#define MMA16816(d, a, b0, b1) \
    asm volatile("mma.sync.aligned.m16n8k16.row.col.f32.f16.f16.f32 " \
                 "{%0,%1,%2,%3}, {%4,%5,%6,%7}, {%8,%9}, {%0,%1,%2,%3};" \
                 : "+f"(d[0]), "+f"(d[1]), "+f"(d[2]), "+f"(d[3]) \
                 : "r"(a[0]), "r"(a[1]), "r"(a[2]), "r"(a[3]), "r"(b0), "r"(b1))

#define STGV4(ptr, v0, v1, v2, v3) \
    asm volatile("st.global.v4.f32 [%0], {%1, %2, %3, %4};" \
                 :: "l"(ptr), "f"(v0), "f"(v1), "f"(v2), "f"(v3) : "memory")

// ---------------- prep: Xh fp16 plane only ----------------
__global__ __launch_bounds__(320, 4)
void prep_kernel(const float* __restrict__ x) {
    const int r = blockIdx.x;          // 0..511
    const int d0 = threadIdx.x * 4;    // 0..1276
    const size_t p = (size_t)r * DDIM + d0;
    float4 xv = *(const float4*)&x[p];
    *(uint2*)&g_Xh[p] = make_uint2(pk2h(xv.x, xv.y), pk2h(xv.z, xv.w));
}

// ---------------- GEMM: one CTA per tile, intra-CTA K-split ----------------
__global__ __launch_bounds__(512, 1)
void pcm_mma_kernel(float* __restrict__ out, const float* __restrict__ W,
                    const float* __restrict__ bias) {
    extern __shared__ char smraw[];
    uint32_t sb = smem_u32(smraw);
    uint32_t base = (sb + 127) & ~127u;
    char* smc = smraw + (base - sb);

    // triangular tile decode
    int t = blockIdx.x, ti = 0;
    while (t >= NTB - ti) { t -= NTB - ti; ++ti; }
    int tj = ti + t;
    const int i0 = ti * 32, j0 = tj * 32;

    const int tid = threadIdx.x;
    const int w = tid >> 5, L = tid & 31;
    const int g = w >> 2;                // K-range group 0..3
    const int gw = w & 3;
    const int plane = gw >> 1;           // k-plane 0/1
    const int warpN = gw & 1;            // N-half
    const int gl = tid & 127;            // group-local tid
    const uint32_t base_g = base + (uint32_t)g * GROUP_BYTES;

    // ---- w-buffer fill (group fills its own 320 words):
    // word idx (within group) = plane*160 + c*32 + q*8 + (kk*2+h)
    // value = (w[d], w[d+1]) halves, d = g*320 + c*64 + kk*16 + h*8 + q*2
    {
        uint32_t* wb = (uint32_t*)(smc + WB_OFF + g * 1280);
#pragma unroll
        for (int u = 0; u < 3; u++) {
            const int idx = gl + u * 128;
            if (idx < 320) {
                const int pl = (idx >= 160) ? 1 : 0;
                const int rr = idx - pl * 160;
                const int c = rr >> 5;
                const int r2 = rr & 31;
                const int q = r2 >> 3;
                const int wd = r2 & 7;
                const int kk = wd >> 1, h = wd & 1;
                const int d = g * KPG + c * 64 + kk * 16 + h * 8 + q * 2;
                wb[idx] = pk2h(W[2 * d + pl], W[2 * (d + 1) + pl]);
            }
        }
    }

    // ---- staged-load assignments (per group): 64 rows x 8 cgroups, 4 per thread
    const __half* src[4];
    uint32_t dst[4];
#pragma unroll
    for (int u = 0; u < 4; u++) {
        const int idx = gl + u * 128;
        const int row = idx >> 3, cg = idx & 7;
        if (row < 32) {                  // A: i-tile X rows
            int gi = i0 + row + 1; if (gi > 511) gi = 511;
            src[u] = &g_Xh[(size_t)gi * DDIM + g * KPG + cg * 8];
            dst[u] = (uint32_t)(row * 128 + ((cg * 16) ^ ((row & 7) * 16)));
        } else {                          // B: j-tile X rows
            const int r = row - 32;
            int gj = j0 + r + 1; if (gj > 511) gj = 511;
            src[u] = &g_Xh[(size_t)gj * DDIM + g * KPG + cg * 8];
            dst[u] = (uint32_t)(SB_OFF + r * 128 + ((cg * 16) ^ ((r & 7) * 16)));
        }
    }

#define LOAD_CHUNK(c) do { \
    const uint32_t stg_ = base_g + ((c) % 3) * STG_BYTES; \
    _Pragma("unroll") \
    for (int u = 0; u < 4; u++) CPA(stg_ + dst[u], src[u] + (c) * KC); \
} while (0)

    // ---- fragment addressing: warp tile 32(i) x 16(j), one plane
    const int a_r0 = (L & 7) + ((L >> 3) & 1) * 8;     // 0..15
    const uint32_t a_cb0 = ((L >> 4) & 1) * 16;
    const uint32_t a_xm = (uint32_t)((a_r0 & 7) * 16);
    const uint32_t aRow0 = (uint32_t)a_r0 * 128;
    const uint32_t aRow1 = (uint32_t)(a_r0 + 16) * 128;
    const int b_r = warpN * 16 + (L & 7) + ((L >> 4) & 1) * 8;
    const uint32_t b_cb0 = ((L >> 3) & 1) * 16;
    const uint32_t b_xm = (uint32_t)((b_r & 7) * 16);
    const uint32_t bRow = SB_OFF + (uint32_t)b_r * 128;
    const uint32_t wBase = base + WB_OFF + (uint32_t)(g * 1280 + plane * 640 + (L & 3) * 32);

    float acc[4][4];
#pragma unroll
    for (int n = 0; n < 4; n++)
#pragma unroll
        for (int e = 0; e < 4; e++) acc[n][e] = 0.f;

    LOAD_CHUNK(0);
    CP_COMMIT();
    LOAD_CHUNK(1);
    CP_COMMIT();

#pragma unroll
    for (int c = 0; c < NCH; c++) {
        if (c + 1 < NCH) CP_WAIT1(); else CP_WAIT0();
        BARG(g);                         // group's chunk c + w-buffer visible

        if (c + 2 < NCH) {
            LOAD_CHUNK(c + 2);
            CP_COMMIT();
        }

        const uint32_t stg = base_g + (c % 3) * STG_BYTES;

        uint32_t wf[8];
        {
            const uint32_t wa = wBase + (uint32_t)(c * 128);
            LDS128(wf[0], wf[1], wf[2], wf[3], wa);
            LDS128(wf[4], wf[5], wf[6], wf[7], wa + 16);
        }

#pragma unroll
        for (int kk = 0; kk < 4; kk++) {
            const uint32_t colA = (a_cb0 + kk * 32) ^ a_xm;
            const uint32_t colB = (b_cb0 + kk * 32) ^ b_xm;
            uint32_t xa0[4], xa1[4], bb[4];
            LDSM4(xa0[0], xa0[1], xa0[2], xa0[3], stg + aRow0 + colA);
            LDSM4(xa1[0], xa1[1], xa1[2], xa1[3], stg + aRow1 + colA);
            LDSM4(bb[0], bb[1], bb[2], bb[3], stg + bRow + colB);

            const uint32_t wlo = wf[kk * 2], whi = wf[kk * 2 + 1];
            uint32_t a0[4], a1[4];
            HMUL2(a0[0], xa0[0], wlo); HMUL2(a0[1], xa0[1], wlo);
            HMUL2(a0[2], xa0[2], whi); HMUL2(a0[3], xa0[3], whi);
            HMUL2(a1[0], xa1[0], wlo); HMUL2(a1[1], xa1[1], wlo);
            HMUL2(a1[2], xa1[2], whi); HMUL2(a1[3], xa1[3], whi);

            MMA16816(acc[0], a0, bb[0], bb[1]);
            MMA16816(acc[1], a0, bb[2], bb[3]);
            MMA16816(acc[2], a1, bb[0], bb[1]);
            MMA16816(acc[3], a1, bb[2], bb[3]);
        }
    }

    // ---- group area dump (64x33 floats in group's own region)
    BARG(g);                             // all group warps done reading stages
    float* area = (float*)(smc + g * GROUP_BYTES);
    {
        const int er = L >> 2, ec = (L & 3) * 2;
        float* dp = &area[(plane * 32 + er) * 33 + warpN * 16 + ec];
        dp[0] = acc[0][0];          dp[1] = acc[0][1];
        dp[8 * 33] = acc[0][2];     dp[8 * 33 + 1] = acc[0][3];
        dp[8] = acc[1][0];          dp[9] = acc[1][1];
        dp[8 * 33 + 8] = acc[1][2]; dp[8 * 33 + 9] = acc[1][3];
        float* dq = dp + 16 * 33;
        dq[0] = acc[2][0];          dq[1] = acc[2][1];
        dq[8 * 33] = acc[2][2];     dq[8 * 33 + 1] = acc[2][3];
        dq[8] = acc[3][0];          dq[9] = acc[3][1];
        dq[8 * 33 + 8] = acc[3][2]; dq[8 * 33 + 9] = acc[3][3];
    }
    __syncthreads();

    // ---- reduce 4 groups + bias -> Ds (64x33: rows 0-31 k0, 32-63 k1)
    const float b0v = bias[0], b1v = bias[1];
    float* Ds = (float*)(smc + DS_OFF);
#pragma unroll
    for (int p = 0; p < 4; p++) {
        const int idx = tid + p * 512;           // 0..2047
        const int r = idx >> 5, cc = idx & 31;
        const float* a0p = (const float*)(smc) + r * 33 + cc;
        float s = a0p[0] + a0p[GROUP_BYTES / 4] + a0p[2 * (GROUP_BYTES / 4)]
                + a0p[3 * (GROUP_BYTES / 4)];
        s += (r >= 32) ? b1v : b0v;
        Ds[r * 33 + cc] = s;
    }
    __syncthreads();

    // ---- writeout: main orientation (512 tasks: r 0..31 x jp 0..15)
    {
        const int jp = tid & 15, r = tid >> 4;
        const int i = i0 + r, j = j0 + 2 * jp;
        if (i < OUTN && j < OUTN) {              // j even -> j+1 <= 509
            float* pp = &out[((size_t)i * OUTN + j) * 2];
            STGV4(pp, Ds[r * 33 + 2 * jp],     Ds[(r + 32) * 33 + 2 * jp],
                      Ds[r * 33 + 2 * jp + 1], Ds[(r + 32) * 33 + 2 * jp + 1]);
        }
    }

    // ---- mirror orientation (skip diagonal tiles)
    if (ti != tj) {
        const int ip = tid & 15, cc = tid >> 4;
        const int jj = j0 + cc, ig = i0 + 2 * ip;   // ig+1 <= 479 < OUTN
        if (jj < OUTN) {
            float* pp = &out[((size_t)jj * OUTN + ig) * 2];
            STGV4(pp, Ds[(2 * ip) * 33 + cc],     Ds[(2 * ip + 32) * 33 + cc],
                      Ds[(2 * ip + 1) * 33 + cc], Ds[(2 * ip + 33) * 33 + cc]);
        }
    }
}

extern "C" void kernel_launch(void* const* d_in, const int* in_sizes, int n_in,
                              void* d_out, int out_size) {
    const float* x = (const float*)d_in[0];   // (1,512,1280) fp32
    const float* W = (const float*)d_in[1];   // (2560,2) fp32
    const float* b = (const float*)d_in[2];   // (2,) fp32
    float* out = (float*)d_out;               // (1,510,510,2) fp32

    prep_kernel<<<512, 320>>>(x);

    cudaFuncSetAttribute(pcm_mma_kernel,
                         cudaFuncAttributeMaxDynamicSharedMemorySize, SMEM_REQ);

    pcm_mma_kernel<<<NTRI, 512, SMEM_REQ>>>(out, W, b);
}